// round 15
// baseline (speedup 1.0000x reference)
#include <cuda_runtime.h>
#include <math.h>

// Problem constants: B=2, T=8, N=65536, M=128, F=5, S=128
#define B_ 2
#define T_ 8
#define N_ 65536
#define M_ 128
#define F_ 5
#define S_ 128
#define GAMMA_ 1.1f

#define NTHREADS 256
#define NWARPS 8
#define SUBPTS 4096                 // points per sub-chunk (16/thread)
#define TAILSC 3                    // sub-chunks per tail iteration
#define NSLOTS (B_ * T_ * M_)       // 2048 output slots
#define TOTALPTS (B_ * T_ * N_)     // 1,048,576
#define TRANSBLKS (TOTALPTS / 4 / NTHREADS)     // 1024
#define SLOTS_PER_THREAD (NSLOTS / NTHREADS)    // 8

// SoA scratch for xy + per-slot precomputed params + execution order.
__device__ __align__(16) float g_x[TOTALPTS];
__device__ __align__(16) float g_y[TOTALPTS];
__device__ float g_cx[NSLOTS];
__device__ float g_cy[NSLOTS];
__device__ float g_thr[NSLOTS];
__device__ int   g_slab[NSLOTS];
__device__ int   g_order[NSLOTS];

// thr = largest float x with sqrtf(x) <= r  => (d2 <= thr) bit-identical to
// (sqrtf(d2) <= r); removes the per-point sqrt.
__device__ __forceinline__ float roi_setup(const float* __restrict__ roi,
                                           float& cx, float& cy)
{
    cx = roi[0];
    cy = roi[1];
    const float hl = __fmul_rn(roi[3], 0.5f);
    const float hw = __fmul_rn(roi[4], 0.5f);
    const float rr = __fmul_rn(
        sqrtf(__fadd_rn(__fmul_rn(hl, hl), __fmul_rn(hw, hw))), GAMMA_);
    float thr = __fmul_rn(rr, rr);
    while (sqrtf(thr) > rr) thr = __int_as_float(__float_as_int(thr) - 1);
    for (;;) {
        float nxt = __int_as_float(__float_as_int(thr) + 1);
        if (sqrtf(nxt) <= rr) thr = nxt; else break;
    }
    return thr;
}

// Merged prep kernel.
// Blocks [0, TRANSBLKS): AoS->SoA transpose (4 points = 5 float4 / thread).
// Block TRANSBLKS: atomic-free classify -- computes per-slot params and a
// DETERMINISTIC straggler-first execution order via a block prefix sum
// (front bucket: score < 0.05, ascending slot order; back bucket: rest,
// descending from the end). Runs concurrently with the transpose blocks.
__global__ __launch_bounds__(NTHREADS)
void prep_kernel(const float4* __restrict__ pts4,
                 const float* __restrict__ rois,
                 const int* __restrict__ vl)
{
    if (blockIdx.x < TRANSBLKS) {
        const int i4 = blockIdx.x * NTHREADS + threadIdx.x;
        const float4 p0 = pts4[i4 * 5 + 0];
        const float4 p1 = pts4[i4 * 5 + 1];
        const float4 p2 = pts4[i4 * 5 + 2];
        const float4 p3 = pts4[i4 * 5 + 3];
        const float4 p4 = pts4[i4 * 5 + 4];
        ((float4*)g_x)[i4] = make_float4(p0.x, p1.y, p2.z, p3.w);
        ((float4*)g_y)[i4] = make_float4(p0.y, p1.z, p2.w, p4.x);
        return;
    }

    // ---- classify block (one block, 256 threads, 8 slots each) ----
    const int tid  = threadIdx.x;
    const int lane = tid & 31;
    const int wid  = tid >> 5;
    __shared__ int s_wf[NWARPS];

    int front[SLOTS_PER_THREAD];
    int fcnt = 0;
    #pragma unroll
    for (int j = 0; j < SLOTS_PER_THREAD; j++) {
        const int slot = tid * SLOTS_PER_THREAD + j;   // (b*T + t)*M + m
        const int m = slot & (M_ - 1);
        const int t = (slot >> 7) & (T_ - 1);
        const int b = slot >> 10;

        int use_t = t;
        if (t != 0 && vl[slot] == 0) use_t = 0;
        const int slab = b * T_ + use_t;

        float cx, cy;
        const float thr = roi_setup(rois + ((size_t)slab * M_ + m) * 7, cx, cy);
        g_cx[slot] = cx;
        g_cy[slot] = cy;
        g_thr[slot] = thr;
        g_slab[slot] = slab;

        // Expected matches/point ~ thr*exp(-|c|^2/2)/2; < 0.05 => deep scan.
        const float score = thr * __expf(-0.5f * (cx * cx + cy * cy));
        front[j] = (score < 0.05f) ? 1 : 0;
        fcnt += front[j];
    }

    // Block-wide exclusive prefix of front counts (slot order preserved).
    int fincl = fcnt;
    #pragma unroll
    for (int d = 1; d < 32; d <<= 1) {
        const int v = __shfl_up_sync(0xFFFFFFFFu, fincl, d);
        if (lane >= d) fincl += v;
    }
    if (lane == 31) s_wf[wid] = fincl;
    __syncthreads();
    int warpOff = 0;
    #pragma unroll
    for (int w = 0; w < NWARPS; w++) {
        if (w < wid) warpOff += s_wf[w];
    }
    int fpos = warpOff + fincl - fcnt;                 // front rank
    int bpos = tid * SLOTS_PER_THREAD - fpos;          // back rank

    #pragma unroll
    for (int j = 0; j < SLOTS_PER_THREAD; j++) {
        const int slot = tid * SLOTS_PER_THREAD + j;
        if (front[j]) g_order[fpos++] = slot;
        else          g_order[NSLOTS - 1 - (bpos++)] = slot;
    }
}

__device__ __forceinline__ unsigned long long spread4(unsigned v)
{
    return (unsigned long long)(v & 0xFFu)
         | ((unsigned long long)(v & 0xFF00u)     << 8)
         | ((unsigned long long)(v & 0xFF0000u)   << 16)
         | ((unsigned long long)(v & 0xFF000000u) << 24);
}

__device__ __forceinline__ unsigned predicate_mask(
    const float4* xv, const float4* yv, float cx, float cy, float thr)
{
    unsigned msk = 0;
    #pragma unroll
    for (int j = 0; j < 4; j++) {
        const float* xs = (const float*)&xv[j];
        const float* ys = (const float*)&yv[j];
        #pragma unroll
        for (int k = 0; k < 4; k++) {
            const float dx = __fsub_rn(xs[k], cx);
            const float dy = __fsub_rn(ys[k], cy);
            const float d2 = __fadd_rn(__fmul_rn(dx, dx), __fmul_rn(dy, dy));
            msk |= (d2 <= thr ? 1u : 0u) << (j * 4 + k);
        }
    }
    return msk;
}

__device__ __forceinline__ unsigned pack_counts(unsigned msk)
{
    unsigned cp = 0;
    #pragma unroll
    for (int j = 0; j < 4; j++)
        cp |= (unsigned)__popc((msk >> (4 * j)) & 0xFu) << (8 * j);
    return cp;
}

// Byte-packed inclusive warp scan (warp-collective; call convergently).
__device__ __forceinline__ unsigned packed_scan(unsigned cp, int lane, unsigned& excl)
{
    unsigned incl = cp;
    #pragma unroll
    for (int d = 1; d < 32; d <<= 1) {
        const unsigned v = __shfl_up_sync(0xFFFFFFFFu, incl, d);
        if (lane >= d) incl += v;
    }
    excl = incl - cp;
    return __shfl_sync(0xFFFFFFFFu, incl, 31);
}

// Ballot-gated scan: skips the 15-shfl chain when no lane matched (the
// common case on straggler deep scans). Convergent for the whole warp.
__device__ __forceinline__ unsigned scan_or_zero(unsigned msk, int lane, unsigned& excl)
{
    if (__ballot_sync(0xFFFFFFFFu, msk != 0) == 0) { excl = 0; return 0; }
    return packed_scan(pack_counts(msk), lane, excl);
}

// Unpack per-warp counts; RECORD this thread's matched point indices into
// the smem rank->index table (no global traffic). Returns chunk total.
__device__ __forceinline__ int record_subchunk(
    const unsigned long long* __restrict__ slotcnt, int wid, int tid,
    unsigned mask, unsigned excl, int total, int ptbase,
    int* __restrict__ s_idx)
{
    unsigned long long tot64 = 0, bef64 = 0;
    #pragma unroll
    for (int w = 0; w < NWARPS; w++) {
        const unsigned long long v = slotcnt[w];
        tot64 += v;
        if (w < wid) bef64 += v;
    }
    const unsigned a = (unsigned)tot64 + (unsigned)(tot64 >> 32);
    const int chunkTotal = (int)((a & 0xFFFFu) + (a >> 16));

    if (mask) {
        int fieldPrefix = 0;
        #pragma unroll
        for (int j = 0; j < 4; j++) {
            const int tj = (int)((tot64 >> (16 * j)) & 0xFFFFu);
            const int bj = (int)((bef64 >> (16 * j)) & 0xFFFFu);
            int r = total + fieldPrefix + bj + (int)((excl >> (8 * j)) & 0xFFu);
            unsigned mj = (mask >> (4 * j)) & 0xFu;
            while (mj) {
                const int k = __ffs(mj) - 1;
                mj &= mj - 1;
                if (r < S_) {
                    s_idx[r] = ptbase + j * (NTHREADS * 4) + tid * 4 + k;
                }
                r++;
            }
            fieldPrefix += tj;
        }
    }
    return chunkTotal;
}

// One CTA per output slot, executed in straggler-first order. The scan loop
// only records matched indices in smem; one coalesced float4 pass at the end
// gathers the 5 fields per match and writes all 640 output floats.
__global__ __launch_bounds__(NTHREADS)
void voxel_pool_kernel(const float* __restrict__ pts, float* __restrict__ out)
{
    const int slot = g_order[blockIdx.x];
    const int m = slot & (M_ - 1);
    const int t = (slot >> 7) & (T_ - 1);
    const int b = slot >> 10;
    const int tid  = threadIdx.x;
    const int lane = tid & 31;
    const int wid  = tid >> 5;

    const int slab = g_slab[slot];
    const float*  P  = pts + (size_t)slab * N_ * F_;
    const float4* X4 = (const float4*)(g_x + (size_t)slab * N_);
    const float4* Y4 = (const float4*)(g_y + (size_t)slab * N_);
    float* O = out + ((size_t)(b * M_ + m) * (T_ * S_) + (size_t)t * S_) * F_;

    __shared__ unsigned long long s_cnt[2][TAILSC][NWARPS];
    __shared__ int s_idx[S_];

    // Chunk-0 loads issued immediately.
    float4 xv0[4], yv0[4];
    #pragma unroll
    for (int j = 0; j < 4; j++) {
        xv0[j] = X4[j * NTHREADS + tid];
        yv0[j] = Y4[j * NTHREADS + tid];
    }

    const float cx  = g_cx[slot];
    const float cy  = g_cy[slot];
    const float thr = g_thr[slot];

    // ---- Chunk 0 (4096 points) ----  (all collectives convergent)
    const unsigned mask0 = predicate_mask(xv0, yv0, cx, cy, thr);
    unsigned excl0;
    const unsigned wt0 = scan_or_zero(mask0, lane, excl0);
    if (lane == 0) s_cnt[0][0][wid] = spread4(wt0);
    __syncthreads();

    int total = record_subchunk(s_cnt[0][0], wid, tid, mask0, excl0, 0, 0, s_idx);

    // ---- Tail: 5 iterations x 3 sub-chunks (12288 pts, one barrier each) ----
    for (int it = 0; it < 5 && total < S_; it++) {
        const int buf = (it & 1) ^ 1;
        const int ptbase = SUBPTS + it * (TAILSC * SUBPTS);

        unsigned masks[TAILSC], excls[TAILSC];
        #pragma unroll
        for (int sc = 0; sc < TAILSC; sc++) {
            const int off4 = (ptbase + sc * SUBPTS) / 4;
            float4 xv[4], yv[4];
            #pragma unroll
            for (int j = 0; j < 4; j++) {
                xv[j] = X4[off4 + j * NTHREADS + tid];
                yv[j] = Y4[off4 + j * NTHREADS + tid];
            }
            masks[sc] = predicate_mask(xv, yv, cx, cy, thr);
            const unsigned wt = scan_or_zero(masks[sc], lane, excls[sc]);
            if (lane == 0) s_cnt[buf][sc][wid] = spread4(wt);
        }
        __syncthreads();

        #pragma unroll
        for (int sc = 0; sc < TAILSC; sc++) {
            if (total < S_) {
                total += record_subchunk(s_cnt[buf][sc], wid, tid,
                                         masks[sc], excls[sc], total,
                                         ptbase + sc * SUBPTS, s_idx);
            }
        }
    }

    // ---- Final emit: gather via s_idx, write 160 float4 (coalesced) ----
    __syncthreads();   // s_idx written by all threads above
    const int written = (total < S_) ? total : S_;
    const int nf4 = (S_ * F_) / 4;                     // 160
    for (int i4 = tid; i4 < nf4; i4 += NTHREADS) {
        float v[4];
        #pragma unroll
        for (int e = 0; e < 4; e++) {
            const int f = i4 * 4 + e;
            const int row = f / F_;
            const int fld = f - row * F_;
            v[e] = (row < written)
                 ? P[(size_t)s_idx[row] * F_ + fld]
                 : 0.0f;
        }
        ((float4*)O)[i4] = make_float4(v[0], v[1], v[2], v[3]);
    }
}

extern "C" void kernel_launch(void* const* d_in, const int* in_sizes, int n_in,
                              void* d_out, int out_size)
{
    const float* pts  = (const float*)d_in[0];  // [B,T,N,F] f32
    const float* rois = (const float*)d_in[1];  // [B,T,M,7] f32
    const int*   vl   = (const int*)d_in[2];    // [B,T,M]   i32
    float* out = (float*)d_out;                 // [B,M,T*S,F] f32

    (void)in_sizes; (void)n_in; (void)out_size;
    prep_kernel<<<TRANSBLKS + 1, NTHREADS>>>((const float4*)pts, rois, vl);
    voxel_pool_kernel<<<NSLOTS, NTHREADS>>>(pts, out);
}

// round 16
// speedup vs baseline: 1.0613x; 1.0613x over previous
#include <cuda_runtime.h>
#include <math.h>

// Problem constants: B=2, T=8, N=65536, M=128, F=5, S=128
#define B_ 2
#define T_ 8
#define N_ 65536
#define M_ 128
#define F_ 5
#define S_ 128
#define GAMMA_ 1.1f

#define NTHREADS 256
#define NWARPS 8
#define SUBPTS 4096                 // points per sub-chunk (16/thread)
#define TAILSC 3                    // sub-chunks per tail iteration
#define NSLOTS (B_ * T_ * M_)       // 2048 output slots
#define TOTALPTS (B_ * T_ * N_)     // 1,048,576
#define TRANSBLKS (TOTALPTS / 4 / NTHREADS)     // 1024
#define SLOTS_PER_THREAD (NSLOTS / NTHREADS)    // 8

// SoA scratch for xy + per-slot precomputed params + execution order.
__device__ __align__(16) float g_x[TOTALPTS];
__device__ __align__(16) float g_y[TOTALPTS];
__device__ float g_cx[NSLOTS];
__device__ float g_cy[NSLOTS];
__device__ float g_thr[NSLOTS];
__device__ int   g_slab[NSLOTS];
__device__ int   g_order[NSLOTS];

// thr = largest float x with sqrtf(x) <= r  => (d2 <= thr) bit-identical to
// (sqrtf(d2) <= r); removes the per-point sqrt.
__device__ __forceinline__ float roi_setup(const float* __restrict__ roi,
                                           float& cx, float& cy)
{
    cx = roi[0];
    cy = roi[1];
    const float hl = __fmul_rn(roi[3], 0.5f);
    const float hw = __fmul_rn(roi[4], 0.5f);
    const float rr = __fmul_rn(
        sqrtf(__fadd_rn(__fmul_rn(hl, hl), __fmul_rn(hw, hw))), GAMMA_);
    float thr = __fmul_rn(rr, rr);
    while (sqrtf(thr) > rr) thr = __int_as_float(__float_as_int(thr) - 1);
    for (;;) {
        float nxt = __int_as_float(__float_as_int(thr) + 1);
        if (sqrtf(nxt) <= rr) thr = nxt; else break;
    }
    return thr;
}

// Merged prep kernel.
// Block 0: atomic-free classify (dispatched FIRST so it overlaps the
//   transpose blocks) -- per-slot params + DETERMINISTIC straggler-first
//   order via a block prefix sum (front: score < 0.05, ascending slot
//   order; back: rest, descending from the end).
// Blocks [1, TRANSBLKS]: AoS->SoA transpose (4 points = 5 float4 / thread).
__global__ __launch_bounds__(NTHREADS)
void prep_kernel(const float4* __restrict__ pts4,
                 const float* __restrict__ rois,
                 const int* __restrict__ vl)
{
    if (blockIdx.x != 0) {
        const int i4 = (blockIdx.x - 1) * NTHREADS + threadIdx.x;
        const float4 p0 = pts4[i4 * 5 + 0];
        const float4 p1 = pts4[i4 * 5 + 1];
        const float4 p2 = pts4[i4 * 5 + 2];
        const float4 p3 = pts4[i4 * 5 + 3];
        const float4 p4 = pts4[i4 * 5 + 4];
        ((float4*)g_x)[i4] = make_float4(p0.x, p1.y, p2.z, p3.w);
        ((float4*)g_y)[i4] = make_float4(p0.y, p1.z, p2.w, p4.x);
        return;
    }

    // ---- classify block (one block, 256 threads, 8 slots each) ----
    const int tid  = threadIdx.x;
    const int lane = tid & 31;
    const int wid  = tid >> 5;
    __shared__ int s_wf[NWARPS];

    int front[SLOTS_PER_THREAD];
    int fcnt = 0;
    #pragma unroll
    for (int j = 0; j < SLOTS_PER_THREAD; j++) {
        const int slot = tid * SLOTS_PER_THREAD + j;   // (b*T + t)*M + m
        const int m = slot & (M_ - 1);
        const int t = (slot >> 7) & (T_ - 1);
        const int b = slot >> 10;

        int use_t = t;
        if (t != 0 && vl[slot] == 0) use_t = 0;
        const int slab = b * T_ + use_t;

        float cx, cy;
        const float thr = roi_setup(rois + ((size_t)slab * M_ + m) * 7, cx, cy);
        g_cx[slot] = cx;
        g_cy[slot] = cy;
        g_thr[slot] = thr;
        g_slab[slot] = slab;

        // Expected matches/point ~ thr*exp(-|c|^2/2)/2; < 0.05 => deep scan.
        const float score = thr * __expf(-0.5f * (cx * cx + cy * cy));
        front[j] = (score < 0.05f) ? 1 : 0;
        fcnt += front[j];
    }

    // Block-wide exclusive prefix of front counts (slot order preserved).
    int fincl = fcnt;
    #pragma unroll
    for (int d = 1; d < 32; d <<= 1) {
        const int v = __shfl_up_sync(0xFFFFFFFFu, fincl, d);
        if (lane >= d) fincl += v;
    }
    if (lane == 31) s_wf[wid] = fincl;
    __syncthreads();
    int warpOff = 0;
    #pragma unroll
    for (int w = 0; w < NWARPS; w++) {
        if (w < wid) warpOff += s_wf[w];
    }
    int fpos = warpOff + fincl - fcnt;                 // front rank
    int bpos = tid * SLOTS_PER_THREAD - fpos;          // back rank

    #pragma unroll
    for (int j = 0; j < SLOTS_PER_THREAD; j++) {
        const int slot = tid * SLOTS_PER_THREAD + j;
        if (front[j]) g_order[fpos++] = slot;
        else          g_order[NSLOTS - 1 - (bpos++)] = slot;
    }
}

__device__ __forceinline__ unsigned long long spread4(unsigned v)
{
    return (unsigned long long)(v & 0xFFu)
         | ((unsigned long long)(v & 0xFF00u)     << 8)
         | ((unsigned long long)(v & 0xFF0000u)   << 16)
         | ((unsigned long long)(v & 0xFF000000u) << 24);
}

__device__ __forceinline__ unsigned predicate_mask(
    const float4* xv, const float4* yv, float cx, float cy, float thr)
{
    unsigned msk = 0;
    #pragma unroll
    for (int j = 0; j < 4; j++) {
        const float* xs = (const float*)&xv[j];
        const float* ys = (const float*)&yv[j];
        #pragma unroll
        for (int k = 0; k < 4; k++) {
            const float dx = __fsub_rn(xs[k], cx);
            const float dy = __fsub_rn(ys[k], cy);
            const float d2 = __fadd_rn(__fmul_rn(dx, dx), __fmul_rn(dy, dy));
            msk |= (d2 <= thr ? 1u : 0u) << (j * 4 + k);
        }
    }
    return msk;
}

__device__ __forceinline__ unsigned pack_counts(unsigned msk)
{
    unsigned cp = 0;
    #pragma unroll
    for (int j = 0; j < 4; j++)
        cp |= (unsigned)__popc((msk >> (4 * j)) & 0xFu) << (8 * j);
    return cp;
}

// Byte-packed inclusive warp scan; returns warp total, sets excl. Must be
// called CONVERGENTLY by all 32 lanes (warp-collective shfls inside).
__device__ __forceinline__ unsigned packed_scan(unsigned cp, int lane, unsigned& excl)
{
    unsigned incl = cp;
    #pragma unroll
    for (int d = 1; d < 32; d <<= 1) {
        const unsigned v = __shfl_up_sync(0xFFFFFFFFu, incl, d);
        if (lane >= d) incl += v;
    }
    excl = incl - cp;
    return __shfl_sync(0xFFFFFFFFu, incl, 31);
}

// Unpack per-warp counts; RECORD this thread's matched point indices into
// the smem rank->index table (no global traffic). Returns chunk total.
__device__ __forceinline__ int record_subchunk(
    const unsigned long long* __restrict__ slotcnt, int wid, int tid,
    unsigned mask, unsigned excl, int total, int ptbase,
    int* __restrict__ s_idx)
{
    unsigned long long tot64 = 0, bef64 = 0;
    #pragma unroll
    for (int w = 0; w < NWARPS; w++) {
        const unsigned long long v = slotcnt[w];
        tot64 += v;
        if (w < wid) bef64 += v;
    }
    const unsigned a = (unsigned)tot64 + (unsigned)(tot64 >> 32);
    const int chunkTotal = (int)((a & 0xFFFFu) + (a >> 16));

    if (mask) {
        int fieldPrefix = 0;
        #pragma unroll
        for (int j = 0; j < 4; j++) {
            const int tj = (int)((tot64 >> (16 * j)) & 0xFFFFu);
            const int bj = (int)((bef64 >> (16 * j)) & 0xFFFFu);
            int r = total + fieldPrefix + bj + (int)((excl >> (8 * j)) & 0xFFu);
            unsigned mj = (mask >> (4 * j)) & 0xFu;
            while (mj) {
                const int k = __ffs(mj) - 1;
                mj &= mj - 1;
                if (r < S_) {
                    s_idx[r] = ptbase + j * (NTHREADS * 4) + tid * 4 + k;
                }
                r++;
            }
            fieldPrefix += tj;
        }
    }
    return chunkTotal;
}

// One CTA per output slot, executed in straggler-first order. Identical to
// the R14 winner: scan records indices in smem; one coalesced scalar pass
// at the end gathers the 5 fields per match and writes all 640 floats.
__global__ __launch_bounds__(NTHREADS)
void voxel_pool_kernel(const float* __restrict__ pts, float* __restrict__ out)
{
    const int slot = g_order[blockIdx.x];
    const int m = slot & (M_ - 1);
    const int t = (slot >> 7) & (T_ - 1);
    const int b = slot >> 10;
    const int tid  = threadIdx.x;
    const int lane = tid & 31;
    const int wid  = tid >> 5;

    const int slab = g_slab[slot];
    const float*  P  = pts + (size_t)slab * N_ * F_;
    const float4* X4 = (const float4*)(g_x + (size_t)slab * N_);
    const float4* Y4 = (const float4*)(g_y + (size_t)slab * N_);
    float* O = out + ((size_t)(b * M_ + m) * (T_ * S_) + (size_t)t * S_) * F_;

    __shared__ unsigned long long s_cnt[2][TAILSC][NWARPS];
    __shared__ int s_idx[S_];

    // Chunk-0 loads issued immediately.
    float4 xv0[4], yv0[4];
    #pragma unroll
    for (int j = 0; j < 4; j++) {
        xv0[j] = X4[j * NTHREADS + tid];
        yv0[j] = Y4[j * NTHREADS + tid];
    }

    const float cx  = g_cx[slot];
    const float cy  = g_cy[slot];
    const float thr = g_thr[slot];

    // ---- Chunk 0 (4096 points) ----  (all collectives convergent)
    const unsigned mask0 = predicate_mask(xv0, yv0, cx, cy, thr);
    unsigned excl0;
    const unsigned wt0 = packed_scan(pack_counts(mask0), lane, excl0);
    if (lane == 0) s_cnt[0][0][wid] = spread4(wt0);
    __syncthreads();

    int total = record_subchunk(s_cnt[0][0], wid, tid, mask0, excl0, 0, 0, s_idx);

    // ---- Tail: 5 iterations x 3 sub-chunks (12288 pts, one barrier each) ----
    for (int it = 0; it < 5 && total < S_; it++) {
        const int buf = (it & 1) ^ 1;
        const int ptbase = SUBPTS + it * (TAILSC * SUBPTS);

        unsigned masks[TAILSC], excls[TAILSC];
        #pragma unroll
        for (int sc = 0; sc < TAILSC; sc++) {
            const int off4 = (ptbase + sc * SUBPTS) / 4;
            float4 xv[4], yv[4];
            #pragma unroll
            for (int j = 0; j < 4; j++) {
                xv[j] = X4[off4 + j * NTHREADS + tid];
                yv[j] = Y4[off4 + j * NTHREADS + tid];
            }
            masks[sc] = predicate_mask(xv, yv, cx, cy, thr);
            const unsigned wt = packed_scan(pack_counts(masks[sc]), lane, excls[sc]);
            if (lane == 0) s_cnt[buf][sc][wid] = spread4(wt);
        }
        __syncthreads();

        #pragma unroll
        for (int sc = 0; sc < TAILSC; sc++) {
            if (total < S_) {
                total += record_subchunk(s_cnt[buf][sc], wid, tid,
                                         masks[sc], excls[sc], total,
                                         ptbase + sc * SUBPTS, s_idx);
            }
        }
    }

    // ---- Final coalesced emit: gather + write all S*F = 640 floats ----
    __syncthreads();   // s_idx written by all threads above
    const int written = (total < S_) ? total : S_;
    #pragma unroll
    for (int base = 0; base < S_ * F_; base += NTHREADS) {
        const int f = base + tid;              // 640 = 2*NTHREADS + 128
        if (f < S_ * F_) {
            const int row = f / F_;
            const int fld = f - row * F_;
            O[f] = (row < written)
                 ? P[(size_t)s_idx[row] * F_ + fld]
                 : 0.0f;
        }
    }
}

extern "C" void kernel_launch(void* const* d_in, const int* in_sizes, int n_in,
                              void* d_out, int out_size)
{
    const float* pts  = (const float*)d_in[0];  // [B,T,N,F] f32
    const float* rois = (const float*)d_in[1];  // [B,T,M,7] f32
    const int*   vl   = (const int*)d_in[2];    // [B,T,M]   i32
    float* out = (float*)d_out;                 // [B,M,T*S,F] f32

    (void)in_sizes; (void)n_in; (void)out_size;
    prep_kernel<<<TRANSBLKS + 1, NTHREADS>>>((const float4*)pts, rois, vl);
    voxel_pool_kernel<<<NSLOTS, NTHREADS>>>(pts, out);
}

// round 17
// speedup vs baseline: 1.0789x; 1.0166x over previous
#include <cuda_runtime.h>
#include <math.h>

// Problem constants: B=2, T=8, N=65536, M=128, F=5, S=128
#define B_ 2
#define T_ 8
#define N_ 65536
#define M_ 128
#define F_ 5
#define S_ 128
#define GAMMA_ 1.1f

#define NTHREADS 256
#define NWARPS 8
#define SUBPTS 4096                 // points per sub-chunk (16/thread)
#define TAILSC 3                    // sub-chunks per tail iteration
#define NSLOTS (B_ * T_ * M_)       // 2048 output slots
#define TOTALPTS (B_ * T_ * N_)     // 1,048,576
#define TRANSBLKS (TOTALPTS / 4 / NTHREADS)     // 1024
#define SLOTS_PER_THREAD (NSLOTS / NTHREADS)    // 8

// SoA scratch for xy + per-slot precomputed params + execution order.
__device__ __align__(16) float g_x[TOTALPTS];
__device__ __align__(16) float g_y[TOTALPTS];
__device__ float g_cx[NSLOTS];
__device__ float g_cy[NSLOTS];
__device__ float g_thr[NSLOTS];
__device__ int   g_slab[NSLOTS];
__device__ int   g_order[NSLOTS];

// ---- packed f32x2 helpers (per-lane exact .rn => bit-identical to scalar) ----
__device__ __forceinline__ unsigned long long pk2(float lo, float hi) {
    unsigned long long r;
    asm("mov.b64 %0, {%1, %2};" : "=l"(r) : "f"(lo), "f"(hi));
    return r;
}
__device__ __forceinline__ unsigned long long sub2(unsigned long long a,
                                                   unsigned long long b) {
    unsigned long long d;
    asm("sub.rn.f32x2 %0, %1, %2;" : "=l"(d) : "l"(a), "l"(b));
    return d;
}
__device__ __forceinline__ unsigned long long mul2(unsigned long long a,
                                                   unsigned long long b) {
    unsigned long long d;
    asm("mul.rn.f32x2 %0, %1, %2;" : "=l"(d) : "l"(a), "l"(b));
    return d;
}
__device__ __forceinline__ unsigned long long add2(unsigned long long a,
                                                   unsigned long long b) {
    unsigned long long d;
    asm("add.rn.f32x2 %0, %1, %2;" : "=l"(d) : "l"(a), "l"(b));
    return d;
}
__device__ __forceinline__ void unpk2(unsigned long long v, float& lo, float& hi) {
    asm("mov.b64 {%0, %1}, %2;" : "=f"(lo), "=f"(hi) : "l"(v));
}

// thr = largest float x with sqrtf(x) <= r  => (d2 <= thr) bit-identical to
// (sqrtf(d2) <= r); removes the per-point sqrt.
__device__ __forceinline__ float roi_setup(const float* __restrict__ roi,
                                           float& cx, float& cy)
{
    cx = roi[0];
    cy = roi[1];
    const float hl = __fmul_rn(roi[3], 0.5f);
    const float hw = __fmul_rn(roi[4], 0.5f);
    const float rr = __fmul_rn(
        sqrtf(__fadd_rn(__fmul_rn(hl, hl), __fmul_rn(hw, hw))), GAMMA_);
    float thr = __fmul_rn(rr, rr);
    while (sqrtf(thr) > rr) thr = __int_as_float(__float_as_int(thr) - 1);
    for (;;) {
        float nxt = __int_as_float(__float_as_int(thr) + 1);
        if (sqrtf(nxt) <= rr) thr = nxt; else break;
    }
    return thr;
}

// Merged prep kernel.
// Block 0: atomic-free classify (dispatched FIRST so it overlaps the
//   transpose blocks) -- per-slot params + DETERMINISTIC straggler-first
//   order via a block prefix sum (front: score < 0.05, ascending slot
//   order; back: rest, descending from the end).
// Blocks [1, TRANSBLKS]: AoS->SoA transpose (4 points = 5 float4 / thread).
__global__ __launch_bounds__(NTHREADS)
void prep_kernel(const float4* __restrict__ pts4,
                 const float* __restrict__ rois,
                 const int* __restrict__ vl)
{
    if (blockIdx.x != 0) {
        const int i4 = (blockIdx.x - 1) * NTHREADS + threadIdx.x;
        const float4 p0 = pts4[i4 * 5 + 0];
        const float4 p1 = pts4[i4 * 5 + 1];
        const float4 p2 = pts4[i4 * 5 + 2];
        const float4 p3 = pts4[i4 * 5 + 3];
        const float4 p4 = pts4[i4 * 5 + 4];
        ((float4*)g_x)[i4] = make_float4(p0.x, p1.y, p2.z, p3.w);
        ((float4*)g_y)[i4] = make_float4(p0.y, p1.z, p2.w, p4.x);
        return;
    }

    // ---- classify block (one block, 256 threads, 8 slots each) ----
    const int tid  = threadIdx.x;
    const int lane = tid & 31;
    const int wid  = tid >> 5;
    __shared__ int s_wf[NWARPS];

    int front[SLOTS_PER_THREAD];
    int fcnt = 0;
    #pragma unroll
    for (int j = 0; j < SLOTS_PER_THREAD; j++) {
        const int slot = tid * SLOTS_PER_THREAD + j;   // (b*T + t)*M + m
        const int m = slot & (M_ - 1);
        const int t = (slot >> 7) & (T_ - 1);
        const int b = slot >> 10;

        int use_t = t;
        if (t != 0 && vl[slot] == 0) use_t = 0;
        const int slab = b * T_ + use_t;

        float cx, cy;
        const float thr = roi_setup(rois + ((size_t)slab * M_ + m) * 7, cx, cy);
        g_cx[slot] = cx;
        g_cy[slot] = cy;
        g_thr[slot] = thr;
        g_slab[slot] = slab;

        // Expected matches/point ~ thr*exp(-|c|^2/2)/2; < 0.05 => deep scan.
        const float score = thr * __expf(-0.5f * (cx * cx + cy * cy));
        front[j] = (score < 0.05f) ? 1 : 0;
        fcnt += front[j];
    }

    // Block-wide exclusive prefix of front counts (slot order preserved).
    int fincl = fcnt;
    #pragma unroll
    for (int d = 1; d < 32; d <<= 1) {
        const int v = __shfl_up_sync(0xFFFFFFFFu, fincl, d);
        if (lane >= d) fincl += v;
    }
    if (lane == 31) s_wf[wid] = fincl;
    __syncthreads();
    int warpOff = 0;
    #pragma unroll
    for (int w = 0; w < NWARPS; w++) {
        if (w < wid) warpOff += s_wf[w];
    }
    int fpos = warpOff + fincl - fcnt;                 // front rank
    int bpos = tid * SLOTS_PER_THREAD - fpos;          // back rank

    #pragma unroll
    for (int j = 0; j < SLOTS_PER_THREAD; j++) {
        const int slot = tid * SLOTS_PER_THREAD + j;
        if (front[j]) g_order[fpos++] = slot;
        else          g_order[NSLOTS - 1 - (bpos++)] = slot;
    }
}

__device__ __forceinline__ unsigned long long spread4(unsigned v)
{
    return (unsigned long long)(v & 0xFFu)
         | ((unsigned long long)(v & 0xFF00u)     << 8)
         | ((unsigned long long)(v & 0xFF0000u)   << 16)
         | ((unsigned long long)(v & 0xFF000000u) << 24);
}

// f32x2 predicate: per 2 points one packed sub/sub/mul/mul/add chain.
// Bit j*4+k corresponds to point <base> + j*1024 + tid*4 + k.
__device__ __forceinline__ unsigned predicate_mask(
    const float4* xv, const float4* yv,
    unsigned long long cx2, unsigned long long cy2, float thr)
{
    unsigned msk = 0;
    #pragma unroll
    for (int j = 0; j < 4; j++) {
        const float4 xq = xv[j];
        const float4 yq = yv[j];
        const unsigned long long dx01 = sub2(pk2(xq.x, xq.y), cx2);
        const unsigned long long dy01 = sub2(pk2(yq.x, yq.y), cy2);
        const unsigned long long dx23 = sub2(pk2(xq.z, xq.w), cx2);
        const unsigned long long dy23 = sub2(pk2(yq.z, yq.w), cy2);
        const unsigned long long d01 = add2(mul2(dx01, dx01), mul2(dy01, dy01));
        const unsigned long long d23 = add2(mul2(dx23, dx23), mul2(dy23, dy23));
        float d0, d1, d2, d3;
        unpk2(d01, d0, d1);
        unpk2(d23, d2, d3);
        msk |= (d0 <= thr ? 1u : 0u) << (j * 4 + 0);
        msk |= (d1 <= thr ? 1u : 0u) << (j * 4 + 1);
        msk |= (d2 <= thr ? 1u : 0u) << (j * 4 + 2);
        msk |= (d3 <= thr ? 1u : 0u) << (j * 4 + 3);
    }
    return msk;
}

__device__ __forceinline__ unsigned pack_counts(unsigned msk)
{
    unsigned cp = 0;
    #pragma unroll
    for (int j = 0; j < 4; j++)
        cp |= (unsigned)__popc((msk >> (4 * j)) & 0xFu) << (8 * j);
    return cp;
}

// Byte-packed inclusive warp scan; returns warp total, sets excl. Must be
// called CONVERGENTLY by all 32 lanes (warp-collective shfls inside).
__device__ __forceinline__ unsigned packed_scan(unsigned cp, int lane, unsigned& excl)
{
    unsigned incl = cp;
    #pragma unroll
    for (int d = 1; d < 32; d <<= 1) {
        const unsigned v = __shfl_up_sync(0xFFFFFFFFu, incl, d);
        if (lane >= d) incl += v;
    }
    excl = incl - cp;
    return __shfl_sync(0xFFFFFFFFu, incl, 31);
}

// Unpack per-warp counts; RECORD this thread's matched point indices into
// the smem rank->index table (no global traffic). Returns chunk total.
__device__ __forceinline__ int record_subchunk(
    const unsigned long long* __restrict__ slotcnt, int wid, int tid,
    unsigned mask, unsigned excl, int total, int ptbase,
    int* __restrict__ s_idx)
{
    unsigned long long tot64 = 0, bef64 = 0;
    #pragma unroll
    for (int w = 0; w < NWARPS; w++) {
        const unsigned long long v = slotcnt[w];
        tot64 += v;
        if (w < wid) bef64 += v;
    }
    const unsigned a = (unsigned)tot64 + (unsigned)(tot64 >> 32);
    const int chunkTotal = (int)((a & 0xFFFFu) + (a >> 16));

    if (mask) {
        int fieldPrefix = 0;
        #pragma unroll
        for (int j = 0; j < 4; j++) {
            const int tj = (int)((tot64 >> (16 * j)) & 0xFFFFu);
            const int bj = (int)((bef64 >> (16 * j)) & 0xFFFFu);
            int r = total + fieldPrefix + bj + (int)((excl >> (8 * j)) & 0xFFu);
            unsigned mj = (mask >> (4 * j)) & 0xFu;
            while (mj) {
                const int k = __ffs(mj) - 1;
                mj &= mj - 1;
                if (r < S_) {
                    s_idx[r] = ptbase + j * (NTHREADS * 4) + tid * 4 + k;
                }
                r++;
            }
            fieldPrefix += tj;
        }
    }
    return chunkTotal;
}

// One CTA per output slot, executed in straggler-first order. The scan loop
// only records matched indices in smem; one coalesced scalar pass at the
// end gathers the 5 fields per match and writes all 640 output floats.
__global__ __launch_bounds__(NTHREADS)
void voxel_pool_kernel(const float* __restrict__ pts, float* __restrict__ out)
{
    const int slot = g_order[blockIdx.x];
    const int m = slot & (M_ - 1);
    const int t = (slot >> 7) & (T_ - 1);
    const int b = slot >> 10;
    const int tid  = threadIdx.x;
    const int lane = tid & 31;
    const int wid  = tid >> 5;

    const int slab = g_slab[slot];
    const float*  P  = pts + (size_t)slab * N_ * F_;
    const float4* X4 = (const float4*)(g_x + (size_t)slab * N_);
    const float4* Y4 = (const float4*)(g_y + (size_t)slab * N_);
    float* O = out + ((size_t)(b * M_ + m) * (T_ * S_) + (size_t)t * S_) * F_;

    __shared__ unsigned long long s_cnt[2][TAILSC][NWARPS];
    __shared__ int s_idx[S_];

    // Chunk-0 loads issued immediately.
    float4 xv0[4], yv0[4];
    #pragma unroll
    for (int j = 0; j < 4; j++) {
        xv0[j] = X4[j * NTHREADS + tid];
        yv0[j] = Y4[j * NTHREADS + tid];
    }

    const float cx  = g_cx[slot];
    const float cy  = g_cy[slot];
    const float thr = g_thr[slot];
    const unsigned long long cx2 = pk2(cx, cx);
    const unsigned long long cy2 = pk2(cy, cy);

    // ---- Chunk 0 (4096 points) ----  (all collectives convergent)
    const unsigned mask0 = predicate_mask(xv0, yv0, cx2, cy2, thr);
    unsigned excl0;
    const unsigned wt0 = packed_scan(pack_counts(mask0), lane, excl0);
    if (lane == 0) s_cnt[0][0][wid] = spread4(wt0);
    __syncthreads();

    int total = record_subchunk(s_cnt[0][0], wid, tid, mask0, excl0, 0, 0, s_idx);

    // ---- Tail: 5 iterations x 3 sub-chunks (12288 pts, one barrier each) ----
    for (int it = 0; it < 5 && total < S_; it++) {
        const int buf = (it & 1) ^ 1;
        const int ptbase = SUBPTS + it * (TAILSC * SUBPTS);

        unsigned masks[TAILSC], excls[TAILSC];
        #pragma unroll
        for (int sc = 0; sc < TAILSC; sc++) {
            const int off4 = (ptbase + sc * SUBPTS) / 4;
            float4 xv[4], yv[4];
            #pragma unroll
            for (int j = 0; j < 4; j++) {
                xv[j] = X4[off4 + j * NTHREADS + tid];
                yv[j] = Y4[off4 + j * NTHREADS + tid];
            }
            masks[sc] = predicate_mask(xv, yv, cx2, cy2, thr);
            const unsigned wt = packed_scan(pack_counts(masks[sc]), lane, excls[sc]);
            if (lane == 0) s_cnt[buf][sc][wid] = spread4(wt);
        }
        __syncthreads();

        #pragma unroll
        for (int sc = 0; sc < TAILSC; sc++) {
            if (total < S_) {
                total += record_subchunk(s_cnt[buf][sc], wid, tid,
                                         masks[sc], excls[sc], total,
                                         ptbase + sc * SUBPTS, s_idx);
            }
        }
    }

    // ---- Final coalesced emit: gather + write all S*F = 640 floats ----
    __syncthreads();   // s_idx written by all threads above
    const int written = (total < S_) ? total : S_;
    #pragma unroll
    for (int base = 0; base < S_ * F_; base += NTHREADS) {
        const int f = base + tid;              // 640 = 2*NTHREADS + 128
        if (f < S_ * F_) {
            const int row = f / F_;
            const int fld = f - row * F_;
            O[f] = (row < written)
                 ? P[(size_t)s_idx[row] * F_ + fld]
                 : 0.0f;
        }
    }
}

extern "C" void kernel_launch(void* const* d_in, const int* in_sizes, int n_in,
                              void* d_out, int out_size)
{
    const float* pts  = (const float*)d_in[0];  // [B,T,N,F] f32
    const float* rois = (const float*)d_in[1];  // [B,T,M,7] f32
    const int*   vl   = (const int*)d_in[2];    // [B,T,M]   i32
    float* out = (float*)d_out;                 // [B,M,T*S,F] f32

    (void)in_sizes; (void)n_in; (void)out_size;
    prep_kernel<<<TRANSBLKS + 1, NTHREADS>>>((const float4*)pts, rois, vl);
    voxel_pool_kernel<<<NSLOTS, NTHREADS>>>(pts, out);
}